// round 16
// baseline (speedup 1.0000x reference)
#include <cuda_runtime.h>
#include <cstdint>
#include <cstddef>

// ============================================================================
// Compile-time basis construction
// ============================================================================
__host__ __device__ constexpr double cexp_(double v) {
    double t = 1.0, s = 1.0;
    for (int n = 1; n < 90; ++n) { t *= v / n; s += t; }
    return s;
}
__host__ __device__ constexpr double csqrt_(double v) {
    if (v <= 0.0) return 0.0;
    double x = v < 1.0 ? 1.0 : v;
    for (int i = 0; i < 80; ++i) x = 0.5 * (x + v / x);
    return x;
}

struct Basis {
    float b0[3][5][5];
    float br[3][2][5][5];
    float bi[3][2][5][5];
};

__host__ __device__ constexpr Basis make_basis() {
    Basis B{};
    for (int yy = 0; yy < 5; ++yy) {
        for (int xx = 0; xx < 5; ++xx) {
            double ys = yy - 2.0, xs = xx - 2.0;
            double r = csqrt_(ys * ys + xs * xs);
            double cth = r > 0.0 ? xs / r : 1.0;
            double sth = r > 0.0 ? ys / r : 0.0;
            double ring0 = cexp_(-(r - 0.0) * (r - 0.0) / 0.72);
            double ring1 = cexp_(-(r - 1.0) * (r - 1.0) / 0.72);
            double ring2 = cexp_(-(r - 2.0) * (r - 2.0) / 0.72);
            B.b0[0][yy][xx] = (float)ring0;
            B.b0[1][yy][xx] = (float)ring1;
            B.b0[2][yy][xx] = (float)ring2;
            double ck = cth, sk = sth;
            for (int k = 0; k < 3; ++k) {
                B.br[k][0][yy][xx] = (float)(ring1 * ck);
                B.br[k][1][yy][xx] = (float)(ring2 * ck);
                B.bi[k][0][yy][xx] = (float)(ring1 * sk);
                B.bi[k][1][yy][xx] = (float)(ring2 * sk);
                double cn = ck * cth - sk * sth;
                double sn = sk * cth + ck * sth;
                ck = cn; sk = sn;
            }
        }
    }
    return B;
}

#define FMA2(acc, a, b) \
    asm("fma.rn.f32x2 %0, %1, %2, %0;" : "+l"(acc) : "l"(a), "l"(b))
#define SPLAT2(dst, f) \
    asm("mov.b64 %0, {%1, %1};" : "=l"(dst) : "f"(f))

// ============================================================================
// Fused kernel, half-size tiles for 2 CTA/SM (cross-CTA phase overlap).
// CTA = 16x8 input tile (halo 18x10, pitch 20) -> 32x16 output, one oh half.
// smem: xs[32][200] 25600B | ysm[72][200] 57600B | ws[8][322] 10304B
//       smR[512] 2048B | smCS[512] float2 4096B      total 99648B
// ============================================================================
__device__ __forceinline__ float dotT(const float (&T)[5][5],
                                      const float (&w)[3][3],
                                      int SY, int SX) {
    float s = 0.f;
#pragma unroll
    for (int dy = 0; dy < 3; ++dy) {
        if (dy < SY) continue;
        int vy = (SY ? 5 : 4) - 2 * dy;
#pragma unroll
        for (int dx = 0; dx < 3; ++dx) {
            if (dx < SX) continue;
            int vx = (SX ? 5 : 4) - 2 * dx;
            float cf = T[vy][vx];
            if (cf != 0.f) s += cf * w[dy][dx];
        }
    }
    return s;
}

__global__ __launch_bounds__(512, 2) void fused(const float* __restrict__ x,
                                                const float* __restrict__ wts,
                                                const float* __restrict__ alpha,
                                                const float* __restrict__ bias,
                                                float* __restrict__ out) {
    constexpr Basis BAS = make_basis();
    extern __shared__ float sm[];
    float*  xs   = sm;                              // [32][200]
    float*  ysm  = sm + 32 * 200;                   // [72][200]
    float*  ws   = sm + (32 + 72) * 200;            // [8][322]
    float*  smR  = sm + (32 + 72) * 200 + 8 * 322;  // [512]
    float2* smCS = (float2*)(smR + 512);            // [512]

    const int tx = blockIdx.x, ty = blockIdx.y;     // tx: 16-col, ty: 8-row tiles
    const int n  = blockIdx.z >> 1;
    const int oh = blockIdx.z & 1;
    const int tid = threadIdx.x;
    const int ix0 = tx * 16, iy0 = ty * 8;

    // ---- Phase A: stage weights + x tile (18x10 halo, pitch 20) -----------
    for (int e = tid; e < 2560; e += 512) {
        int o = e / 320, r = e % 320, i = r / 10, c = r % 10;
        ws[o * 322 + i * 10 + c] =
            (c < 9) ? wts[(oh * 8 + o) * 288 + i * 9 + c] : 0.f;
    }
    const float* xg = x + (size_t)n * 32 * 36864;
    const bool interior = (tx > 0) & (tx < 11) & (ty > 0) & (ty < 23);
    if (interior) {
        for (int e = tid; e < 5760; e += 512) {
            int i = e / 180, rem = e % 180, r = rem / 18, cc = rem % 18;
            xs[i * 200 + r * 20 + cc] =
                xg[(size_t)i * 36864 + (iy0 - 1 + r) * 192 + (ix0 - 1 + cc)];
        }
    } else {
        for (int e = tid; e < 5760; e += 512) {
            int i = e / 180, rem = e % 180, r = rem / 18, cc = rem % 18;
            int gy = iy0 - 1 + r, gx = ix0 - 1 + cc;
            float v = 0.f;
            if ((unsigned)gy < 192u && (unsigned)gx < 192u)
                v = xg[(size_t)i * 36864 + gy * 192 + gx];
            xs[i * 200 + r * 20 + cc] = v;
        }
    }
    __syncthreads();

    // ---- Phase B: channel mix (tid<400) | modulation staging (tid>=400) ---
    {
        const int o1 = tid & 7;
        const int pg = tid >> 3;
        if (pg < 50) {
            const int px0 = pg * 4;
            unsigned long long acc2[5][4];
#pragma unroll
            for (int p = 0; p < 5; ++p)
#pragma unroll
                for (int j = 0; j < 4; ++j) acc2[p][j] = 0ULL;

            const float* xp = xs + px0;
            const float* wg = ws + o1 * 322;

#pragma unroll 4
            for (int i = 0; i < 32; ++i) {
                float4 xv = *(const float4*)(xp + i * 200);
                unsigned long long x0, x1, x2, x3;
                SPLAT2(x0, xv.x); SPLAT2(x1, xv.y);
                SPLAT2(x2, xv.z); SPLAT2(x3, xv.w);
                unsigned long long xa[4] = {x0, x1, x2, x3};
#pragma unroll
                for (int p = 0; p < 5; ++p) {
                    unsigned long long w2 =
                        *(const unsigned long long*)(wg + i * 10 + p * 2);
#pragma unroll
                    for (int j = 0; j < 4; ++j) FMA2(acc2[p][j], w2, xa[j]);
                }
            }

            float* yb = ysm + o1 * 9 * 200 + px0;
#pragma unroll
            for (int p = 0; p < 5; ++p) {
                float lo[4], hi[4];
#pragma unroll
                for (int j = 0; j < 4; ++j) {
                    uint2 u = *(uint2*)&acc2[p][j];
                    lo[j] = __uint_as_float(u.x);
                    hi[j] = __uint_as_float(u.y);
                }
                *(float4*)(yb + (size_t)(2 * p) * 200) =
                    make_float4(lo[0], lo[1], lo[2], lo[3]);
                if (p < 4)
                    *(float4*)(yb + (size_t)(2 * p + 1) * 200) =
                        make_float4(hi[0], hi[1], hi[2], hi[3]);
            }
        } else {
            // modulation staging: rho, c1, s1 for the 32x16 output px
            const int idx = tid - 400;   // 0..111
            const float* a0b = alpha + (size_t)n * 147456;
            const float* a1b = a0b + (size_t)8 * 147456;
            for (int e = idx; e < 512; e += 112) {
                int pyy = e >> 5, pxx = e & 31;   // 16 rows x 32 cols
                size_t go = (size_t)(ty * 16 + pyy) * 384 + tx * 32 + pxx;
                float a0 = a0b[go];
                float a1 = a1b[go];
                float rho = sqrtf(a0 * a0 + a1 * a1);
                float inv = 1.0f / (rho + 1e-8f);
                smR[e] = rho;
                smCS[e] = make_float2(a0 * inv, a1 * inv);
            }
        }
    }
    __syncthreads();

    // ---- Phase C: taps + modulation + rho/bias epilogue -------------------
    const int q  = tid & 127;      // 128 quads: 8 (qy) x 16 (qx)
    const int os = tid >> 7;       // 0..3, 2 ol each
    const int qy = q >> 4, qx = q & 15;
    const int py0 = ty * 16 + 2 * qy;
    const int px0 = tx * 32 + 2 * qx;
    const int e00 = (2 * qy) * 32 + 2 * qx;   // modulation table index

#pragma unroll
    for (int oi = 0; oi < 2; ++oi) {
        const int ol = os * 2 + oi;
        const int o  = oh * 8 + ol;
        float acc[2][2] = {{0.f, 0.f}, {0.f, 0.f}};
        float ck[2][2], sk[2][2];
#pragma unroll
        for (int sy = 0; sy < 2; ++sy)
#pragma unroll
            for (int sx = 0; sx < 2; ++sx) {
                float2 cs = smCS[e00 + sy * 32 + sx];
                ck[sy][sx] = cs.x; sk[sy][sx] = cs.y;
            }

#pragma unroll
        for (int c = 0; c < 9; ++c) {
            if (c == 5 || c == 7) {
#pragma unroll
                for (int sy = 0; sy < 2; ++sy)
#pragma unroll
                    for (int sx = 0; sx < 2; ++sx) {
                        float2 cs = smCS[e00 + sy * 32 + sx];
                        float cn = ck[sy][sx] * cs.x - sk[sy][sx] * cs.y;
                        float sn = sk[sy][sx] * cs.x + ck[sy][sx] * cs.y;
                        ck[sy][sx] = cn; sk[sy][sx] = sn;
                    }
            }
            const float* wbp = ysm + (ol * 9 + c) * 200 + qy * 20 + qx;
            float w[3][3];
#pragma unroll
            for (int dy = 0; dy < 3; ++dy)
#pragma unroll
                for (int dx = 0; dx < 3; ++dx) w[dy][dx] = wbp[dy * 20 + dx];

            if (c < 3) {
                acc[0][0] += dotT(BAS.b0[c], w, 0, 0);
                acc[0][1] += dotT(BAS.b0[c], w, 0, 1);
                acc[1][0] += dotT(BAS.b0[c], w, 1, 0);
                acc[1][1] += dotT(BAS.b0[c], w, 1, 1);
            } else {
                const int k = (c - 3) >> 1;
                const int j = (c - 3) & 1;
#pragma unroll
                for (int sy = 0; sy < 2; ++sy)
#pragma unroll
                    for (int sx = 0; sx < 2; ++sx) {
                        float dR = dotT(BAS.br[k][j], w, sy, sx);
                        float dI = dotT(BAS.bi[k][j], w, sy, sx);
                        acc[sy][sx] += dR * ck[sy][sx] + dI * sk[sy][sx];
                    }
            }
        }
        float bo = bias[o];
#pragma unroll
        for (int sy = 0; sy < 2; ++sy) {
            float2 v;
            v.x = smR[e00 + sy * 32 + 0] * acc[sy][0] + bo;
            v.y = smR[e00 + sy * 32 + 1] * acc[sy][1] + bo;
            *(float2*)(out + ((size_t)(n * 16 + o)) * 147456 +
                       (size_t)(py0 + sy) * 384 + px0) = v;
        }
    }
}

// ============================================================================
// Launch
// ============================================================================
extern "C" void kernel_launch(void* const* d_in, const int* in_sizes, int n_in,
                              void* d_out, int out_size) {
    const float* x     = (const float*)d_in[0];  // (8,32,192,192)
    const float* alpha = (const float*)d_in[1];  // (2,8,1,384,384)
    const float* wts   = (const float*)d_in[2];  // (16,32,9)
    const float* bias  = (const float*)d_in[3];  // (16,)
    float* out = (float*)d_out;                  // (8,16,384,384)

    (void)in_sizes; (void)n_in; (void)out_size;

    const int smem = ((32 + 72) * 200 + 8 * 322 + 512 + 1024) * 4;  // 99648 B
    cudaFuncSetAttribute(fused, cudaFuncAttributeMaxDynamicSharedMemorySize, smem);

    fused<<<dim3(12, 24, 16), 512, smem>>>(x, wts, alpha, bias, out);
}

// round 17
// speedup vs baseline: 1.1495x; 1.1495x over previous
#include <cuda_runtime.h>
#include <cuda_bf16.h>
#include <cstdint>
#include <cstddef>

// ============================================================================
// Compile-time basis construction
// ============================================================================
__host__ __device__ constexpr double cexp_(double v) {
    double t = 1.0, s = 1.0;
    for (int n = 1; n < 90; ++n) { t *= v / n; s += t; }
    return s;
}
__host__ __device__ constexpr double csqrt_(double v) {
    if (v <= 0.0) return 0.0;
    double x = v < 1.0 ? 1.0 : v;
    for (int i = 0; i < 80; ++i) x = 0.5 * (x + v / x);
    return x;
}

struct Basis {
    float b0[3][5][5];
    float br[3][2][5][5];
    float bi[3][2][5][5];
};

__host__ __device__ constexpr Basis make_basis() {
    Basis B{};
    for (int yy = 0; yy < 5; ++yy) {
        for (int xx = 0; xx < 5; ++xx) {
            double ys = yy - 2.0, xs = xx - 2.0;
            double r = csqrt_(ys * ys + xs * xs);
            double cth = r > 0.0 ? xs / r : 1.0;
            double sth = r > 0.0 ? ys / r : 0.0;
            double ring0 = cexp_(-(r - 0.0) * (r - 0.0) / 0.72);
            double ring1 = cexp_(-(r - 1.0) * (r - 1.0) / 0.72);
            double ring2 = cexp_(-(r - 2.0) * (r - 2.0) / 0.72);
            B.b0[0][yy][xx] = (float)ring0;
            B.b0[1][yy][xx] = (float)ring1;
            B.b0[2][yy][xx] = (float)ring2;
            double ck = cth, sk = sth;
            for (int k = 0; k < 3; ++k) {
                B.br[k][0][yy][xx] = (float)(ring1 * ck);
                B.br[k][1][yy][xx] = (float)(ring2 * ck);
                B.bi[k][0][yy][xx] = (float)(ring1 * sk);
                B.bi[k][1][yy][xx] = (float)(ring2 * sk);
                double cn = ck * cth - sk * sth;
                double sn = sk * cth + ck * sth;
                ck = cn; sk = sn;
            }
        }
    }
    return B;
}

// ============================================================================
// Tensor-core helpers (mma.sync m16n8k16 bf16, fp32 accum)
// ============================================================================
__device__ __forceinline__ uint32_t bfpack(__nv_bfloat16 a, __nv_bfloat16 b) {
    __nv_bfloat162 t; t.x = a; t.y = b;   // low half = a (smaller k index)
    return *reinterpret_cast<uint32_t*>(&t);
}

#define MMA_BF16(d0,d1,d2,d3, a0,a1,a2,a3, b0,b1) \
    asm("mma.sync.aligned.m16n8k16.row.col.f32.bf16.bf16.f32 " \
        "{%0,%1,%2,%3}, {%4,%5,%6,%7}, {%8,%9}, {%0,%1,%2,%3};" \
        : "+f"(d0), "+f"(d1), "+f"(d2), "+f"(d3) \
        : "r"(a0), "r"(a1), "r"(a2), "r"(a3), "r"(b0), "r"(b1))

#define LDMATRIX_X4_TRANS(r0,r1,r2,r3, addr) \
    asm("ldmatrix.sync.aligned.m8n8.x4.trans.shared.b16 {%0,%1,%2,%3}, [%4];" \
        : "=r"(r0), "=r"(r1), "=r"(r2), "=r"(r3) : "r"(addr) : "memory")

// ============================================================================
// Fused kernel. CTA = 16x16 input tile -> 32x32 output tile, one oh half.
// Phase B = tensor-core GEMM ysm[72ch][360px] = W[72x32] @ X[32x360px],
// bf16 hi/lo split (3 products), mma.sync m16n8k16.
// smem (bytes): ysm 103680 | xh 24064 | xl 24064 | wsm 10752 | smR 4096 |
//               smCS 8192   -> total 174848, 1 CTA/SM.
// ============================================================================
__device__ __forceinline__ float dotT(const float (&T)[5][5],
                                      const float (&w)[3][3],
                                      int SY, int SX) {
    float s = 0.f;
#pragma unroll
    for (int dy = 0; dy < 3; ++dy) {
        if (dy < SY) continue;
        int vy = (SY ? 5 : 4) - 2 * dy;
#pragma unroll
        for (int dx = 0; dx < 3; ++dx) {
            if (dx < SX) continue;
            int vx = (SX ? 5 : 4) - 2 * dx;
            float cf = T[vy][vx];
            if (cf != 0.f) s += cf * w[dy][dx];
        }
    }
    return s;
}

__global__ __launch_bounds__(1024, 1) void fused(const float* __restrict__ x,
                                                 const float* __restrict__ wts,
                                                 const float* __restrict__ alpha,
                                                 const float* __restrict__ bias,
                                                 float* __restrict__ out) {
    constexpr Basis BAS = make_basis();
    extern __shared__ char smc[];
    float*         ysm  = (float*)smc;                       // [72][360]
    __nv_bfloat16* xh   = (__nv_bfloat16*)(smc + 103680);    // [32][376]
    __nv_bfloat16* xl   = (__nv_bfloat16*)(smc + 127744);    // [32][376]
    float*         wsm  = (float*)(smc + 151808);            // [32][84]
    float*         smR  = (float*)(smc + 162560);            // [1024]
    float2*        smCS = (float2*)(smc + 166656);           // [1024]

    const int tx = blockIdx.x, ty = blockIdx.y;
    const int n  = blockIdx.z >> 1;
    const int oh = blockIdx.z & 1;
    const int tid = threadIdx.x;
    const int ix0 = tx * 16, iy0 = ty * 16;

    // ---- Phase A0: zero bf16 x arrays (pads must be 0) --------------------
    {
        uint4* z = (uint4*)xh;   // xh+xl contiguous: 48128 B = 3008 uint4
        for (int e = tid; e < 3008; e += 1024) z[e] = make_uint4(0, 0, 0, 0);
    }
    // weights -> wsm[k][o1*9+c], pitch 84
    for (int e = tid; e < 2304; e += 1024) {
        int o1 = e / 288, r = e % 288, i = r / 9, c = r % 9;
        wsm[i * 84 + o1 * 9 + c] = wts[(oh * 8 + o1) * 288 + r];
    }
    // modulation table for this 32x32 output tile
    {
        int pyy = tid >> 5, pxx = tid & 31;
        size_t go = (size_t)(ty * 32 + pyy) * 384 + tx * 32 + pxx;
        const float* a0b = alpha + (size_t)n * 147456;
        float a0 = a0b[go];
        float a1 = a0b[go + (size_t)8 * 147456];
        float rho = sqrtf(a0 * a0 + a1 * a1);
        float inv = 1.0f / (rho + 1e-8f);
        smR[tid] = rho;
        smCS[tid] = make_float2(a0 * inv, a1 * inv);
    }
    __syncthreads();   // zero-fill complete before interior writes

    // ---- Phase A1: stage x tile as bf16 hi/lo (18x18 halo, pitch 20) ------
    const float* xg = x + (size_t)n * 32 * 36864;
    const bool interior = (tx > 0) & (tx < 11) & (ty > 0) & (ty < 11);
    if (interior) {
        for (int e = tid; e < 10368; e += 1024) {
            int i = e / 324, rem = e % 324, r = rem / 18, cc = rem % 18;
            float v = xg[(size_t)i * 36864 + (iy0 - 1 + r) * 192 + (ix0 - 1 + cc)];
            __nv_bfloat16 h = __float2bfloat16(v);
            xh[i * 376 + r * 20 + cc] = h;
            xl[i * 376 + r * 20 + cc] = __float2bfloat16(v - __bfloat162float(h));
        }
    } else {
        for (int e = tid; e < 10368; e += 1024) {
            int i = e / 324, rem = e % 324, r = rem / 18, cc = rem % 18;
            int gy = iy0 - 1 + r, gx = ix0 - 1 + cc;
            float v = 0.f;
            if ((unsigned)gy < 192u && (unsigned)gx < 192u)
                v = xg[(size_t)i * 36864 + gy * 192 + gx];
            __nv_bfloat16 h = __float2bfloat16(v);
            xh[i * 376 + r * 20 + cc] = h;
            xl[i * 376 + r * 20 + cc] = __float2bfloat16(v - __bfloat162float(h));
        }
    }
    __syncthreads();

    // ---- Phase B: tensor-core GEMM  ysm = W @ X  --------------------------
    {
        const int warp = tid >> 5, lane = tid & 31;
        const uint32_t xh_base = (uint32_t)__cvta_generic_to_shared(xh);
        const uint32_t xl_base = (uint32_t)__cvta_generic_to_shared(xl);
        const int trow = lane & 7, tsel = lane >> 3;
        const int lrow = ((tsel & 2) ? 8 : 0) + trow;   // k row within chunk
        const int lcol_off = (tsel & 1) ? 8 : 0;        // px offset within tile

        for (int u = warp; u < 207; u += 32) {          // 23 m-tiles x 9 n-chunks
            int mt = u % 23, nc = u / 23;
            int px0 = mt * 16, n0 = nc * 8;
            float d0 = 0.f, d1 = 0.f, d2 = 0.f, d3 = 0.f;
#pragma unroll
            for (int kc = 0; kc < 2; ++kc) {
                int k0 = kc * 16;
                uint32_t off = (uint32_t)(((k0 + lrow) * 376 + px0 + lcol_off) * 2);
                uint32_t ah0, ah1, ah2, ah3, al0, al1, al2, al3;
                LDMATRIX_X4_TRANS(ah0, ah1, ah2, ah3, xh_base + off);
                LDMATRIX_X4_TRANS(al0, al1, al2, al3, xl_base + off);

                // B fragment from fp32 W, bf16 hi/lo split
                int kb = k0 + 2 * (lane & 3);
                int nn = n0 + (lane >> 2);
                float w0 = wsm[kb * 84 + nn];
                float w1 = wsm[(kb + 1) * 84 + nn];
                float w8 = wsm[(kb + 8) * 84 + nn];
                float w9 = wsm[(kb + 9) * 84 + nn];
                __nv_bfloat16 h0 = __float2bfloat16(w0);
                __nv_bfloat16 h1 = __float2bfloat16(w1);
                __nv_bfloat16 h8 = __float2bfloat16(w8);
                __nv_bfloat16 h9 = __float2bfloat16(w9);
                uint32_t bh0 = bfpack(h0, h1), bh1 = bfpack(h8, h9);
                uint32_t bl0 = bfpack(__float2bfloat16(w0 - __bfloat162float(h0)),
                                      __float2bfloat16(w1 - __bfloat162float(h1)));
                uint32_t bl1 = bfpack(__float2bfloat16(w8 - __bfloat162float(h8)),
                                      __float2bfloat16(w9 - __bfloat162float(h9)));

                MMA_BF16(d0, d1, d2, d3, ah0, ah1, ah2, ah3, bh0, bh1);
                MMA_BF16(d0, d1, d2, d3, al0, al1, al2, al3, bh0, bh1);
                MMA_BF16(d0, d1, d2, d3, ah0, ah1, ah2, ah3, bl0, bl1);
            }
            // store D: lane holds (px0+l>>2, n0+2(l&3)+{0,1}) and +8 rows
            int prow = px0 + (lane >> 2);
            int pcol = n0 + 2 * (lane & 3);
            ysm[pcol * 360 + prow]       = d0;
            ysm[(pcol + 1) * 360 + prow] = d1;
            if (px0 != 352) {
                ysm[pcol * 360 + prow + 8]       = d2;
                ysm[(pcol + 1) * 360 + prow + 8] = d3;
            }
        }
    }
    __syncthreads();

    // ---- Phase C: taps + modulation + rho/bias epilogue -------------------
    const int q  = tid & 255;
    const int os = tid >> 8;       // 0..3, 2 ol each
    const int qy = q >> 4, qx = q & 15;
    const int py0 = ty * 32 + 2 * qy;
    const int px0 = tx * 32 + 2 * qx;
    const int e00 = (2 * qy) * 32 + 2 * qx;

#pragma unroll
    for (int oi = 0; oi < 2; ++oi) {
        const int ol = os * 2 + oi;
        const int o  = oh * 8 + ol;
        float acc[2][2] = {{0.f, 0.f}, {0.f, 0.f}};
        float ck[2][2], sk[2][2];
#pragma unroll
        for (int sy = 0; sy < 2; ++sy)
#pragma unroll
            for (int sx = 0; sx < 2; ++sx) {
                float2 cs = smCS[e00 + sy * 32 + sx];
                ck[sy][sx] = cs.x; sk[sy][sx] = cs.y;
            }

#pragma unroll
        for (int c = 0; c < 9; ++c) {
            if (c == 5 || c == 7) {
#pragma unroll
                for (int sy = 0; sy < 2; ++sy)
#pragma unroll
                    for (int sx = 0; sx < 2; ++sx) {
                        float2 cs = smCS[e00 + sy * 32 + sx];
                        float cn = ck[sy][sx] * cs.x - sk[sy][sx] * cs.y;
                        float sn = sk[sy][sx] * cs.x + ck[sy][sx] * cs.y;
                        ck[sy][sx] = cn; sk[sy][sx] = sn;
                    }
            }
            const float* wbp = ysm + (ol * 9 + c) * 360 + qy * 20 + qx;
            float w[3][3];
#pragma unroll
            for (int dy = 0; dy < 3; ++dy)
#pragma unroll
                for (int dx = 0; dx < 3; ++dx) w[dy][dx] = wbp[dy * 20 + dx];

            if (c < 3) {
                acc[0][0] += dotT(BAS.b0[c], w, 0, 0);
                acc[0][1] += dotT(BAS.b0[c], w, 0, 1);
                acc[1][0] += dotT(BAS.b0[c], w, 1, 0);
                acc[1][1] += dotT(BAS.b0[c], w, 1, 1);
            } else {
                const int k = (c - 3) >> 1;
                const int j = (c - 3) & 1;
#pragma unroll
                for (int sy = 0; sy < 2; ++sy)
#pragma unroll
                    for (int sx = 0; sx < 2; ++sx) {
                        float dR = dotT(BAS.br[k][j], w, sy, sx);
                        float dI = dotT(BAS.bi[k][j], w, sy, sx);
                        acc[sy][sx] += dR * ck[sy][sx] + dI * sk[sy][sx];
                    }
            }
        }
        float bo = bias[o];
#pragma unroll
        for (int sy = 0; sy < 2; ++sy) {
            float2 v;
            v.x = smR[e00 + sy * 32 + 0] * acc[sy][0] + bo;
            v.y = smR[e00 + sy * 32 + 1] * acc[sy][1] + bo;
            *(float2*)(out + ((size_t)(n * 16 + o)) * 147456 +
                       (size_t)(py0 + sy) * 384 + px0) = v;
        }
    }
}

// ============================================================================
// Launch
// ============================================================================
extern "C" void kernel_launch(void* const* d_in, const int* in_sizes, int n_in,
                              void* d_out, int out_size) {
    const float* x     = (const float*)d_in[0];  // (8,32,192,192)
    const float* alpha = (const float*)d_in[1];  // (2,8,1,384,384)
    const float* wts   = (const float*)d_in[2];  // (16,32,9)
    const float* bias  = (const float*)d_in[3];  // (16,)
    float* out = (float*)d_out;                  // (8,16,384,384)

    (void)in_sizes; (void)n_in; (void)out_size;

    const int smem = 174848;
    cudaFuncSetAttribute(fused, cudaFuncAttributeMaxDynamicSharedMemorySize, smem);

    fused<<<dim3(12, 12, 16), 1024, smem>>>(x, wts, alpha, bias, out);
}